// round 1
// baseline (speedup 1.0000x reference)
#include <cuda_runtime.h>

#define HW 4096
#define CDIM 64
#define BM 64
#define BN 64
#define NB 8
#define NTILES (HW / BN)

// XOR-swizzled index for the k-major V copy: element (k, c) of the 64x64 tile.
// float4-granular swizzle keeps reads of V2[k][4tx..4tx+3] conflict-free and
// cuts transpose-store conflicts to 4-way.
__device__ __forceinline__ int v2swz(int k, int c) {
    return k * 64 + ((((c >> 2) ^ (k & 15)) << 2) | (c & 3));
}

__global__ __launch_bounds__(256) void attn_kernel(const float* __restrict__ X,
                                                   float* __restrict__ out) {
    __shared__ float Qs[64 * 64];   // Qs[c*64+q]   (c-major Q tile)
    __shared__ float KPs[64 * 64];  // KV tile (c-major) during gemm1, P tile [q][k] during gemm2
    __shared__ float V2[64 * 64];   // V tile, k-major, swizzled

    const int n  = blockIdx.y;
    const int q0 = blockIdx.x * BM;
    const int tid = threadIdx.x;
    const int tx = tid & 15;   // gemm1: key sub-tile; gemm2: out-channel sub-tile
    const int ty = tid >> 4;   // query sub-tile

    const float* Xn = X + (size_t)n * CDIM * HW;

    // ---- load Q tile (coalesced float4 per c-row) ----
#pragma unroll
    for (int i = 0; i < 4; i++) {
        int idx = tid + i * 256;
        int c = idx >> 4;
        int q4 = idx & 15;
        float4 v = *reinterpret_cast<const float4*>(Xn + c * HW + q0 + q4 * 4);
        *reinterpret_cast<float4*>(Qs + c * 64 + q4 * 4) = v;
    }

    float o[4][4];
    float m[4], l[4];
#pragma unroll
    for (int j = 0; j < 4; j++) {
        m[j] = -1e30f;
        l[j] = 0.0f;
#pragma unroll
        for (int i = 0; i < 4; i++) o[j][i] = 0.0f;
    }

    for (int t = 0; t < NTILES; t++) {
        const int kb = t * BN;
        __syncthreads();  // previous iteration's P/V2 readers must finish
        // ---- load KV tile: one gmem read feeds both smem layouts (K == V) ----
#pragma unroll
        for (int i = 0; i < 4; i++) {
            int idx = tid + i * 256;
            int c = idx >> 4;
            int k4 = idx & 15;
            float4 v = *reinterpret_cast<const float4*>(Xn + c * HW + kb + k4 * 4);
            *reinterpret_cast<float4*>(KPs + c * 64 + k4 * 4) = v;
            V2[v2swz(k4 * 4 + 0, c)] = v.x;
            V2[v2swz(k4 * 4 + 1, c)] = v.y;
            V2[v2swz(k4 * 4 + 2, c)] = v.z;
            V2[v2swz(k4 * 4 + 3, c)] = v.w;
        }
        __syncthreads();

        // ---- gemm1: S[4q][4k] = Q Kᵀ (sum over c) ----
        float s[4][4];
#pragma unroll
        for (int j = 0; j < 4; j++)
#pragma unroll
            for (int i = 0; i < 4; i++) s[j][i] = 0.0f;

#pragma unroll 16
        for (int c = 0; c < 64; c++) {
            float4 qv = *reinterpret_cast<const float4*>(Qs + c * 64 + ty * 4);
            float4 kv = *reinterpret_cast<const float4*>(KPs + c * 64 + tx * 4);
            float qa[4] = {qv.x, qv.y, qv.z, qv.w};
            float ka[4] = {kv.x, kv.y, kv.z, kv.w};
#pragma unroll
            for (int j = 0; j < 4; j++)
#pragma unroll
                for (int i = 0; i < 4; i++) s[j][i] = fmaf(qa[j], ka[i], s[j][i]);
        }

        // ---- online softmax (row stats across the 16 tx lanes via shfl) ----
#pragma unroll
        for (int j = 0; j < 4; j++) {
            float rmax = fmaxf(fmaxf(s[j][0], s[j][1]), fmaxf(s[j][2], s[j][3]));
#pragma unroll
            for (int w = 1; w < 16; w <<= 1)
                rmax = fmaxf(rmax, __shfl_xor_sync(0xffffffffu, rmax, w));
            float mn = fmaxf(m[j], rmax);
            float corr = __expf(m[j] - mn);
            float rsum = 0.0f;
#pragma unroll
            for (int i = 0; i < 4; i++) {
                s[j][i] = __expf(s[j][i] - mn);
                rsum += s[j][i];
            }
#pragma unroll
            for (int w = 1; w < 16; w <<= 1)
                rsum += __shfl_xor_sync(0xffffffffu, rsum, w);
            l[j] = l[j] * corr + rsum;
            m[j] = mn;
#pragma unroll
            for (int i = 0; i < 4; i++) o[j][i] *= corr;
        }

        __syncthreads();  // all gemm1 KV reads done before P overwrites the buffer
#pragma unroll
        for (int j = 0; j < 4; j++)
            *reinterpret_cast<float4*>(KPs + (ty * 4 + j) * 64 + tx * 4) =
                make_float4(s[j][0], s[j][1], s[j][2], s[j][3]);
        __syncthreads();

        // ---- gemm2: O[4q][4c] += P V  (k-chunked: P reads are float4 broadcasts) ----
#pragma unroll 4
        for (int kc = 0; kc < 16; kc++) {
            float pr[4][4];
#pragma unroll
            for (int j = 0; j < 4; j++) {
                float4 pv = *reinterpret_cast<const float4*>(KPs + (ty * 4 + j) * 64 + kc * 4);
                pr[j][0] = pv.x; pr[j][1] = pv.y; pr[j][2] = pv.z; pr[j][3] = pv.w;
            }
#pragma unroll
            for (int kk = 0; kk < 4; kk++) {
                int k = kc * 4 + kk;
                float4 vv = *reinterpret_cast<const float4*>(V2 + k * 64 + ((tx ^ (k & 15)) << 2));
                float va[4] = {vv.x, vv.y, vv.z, vv.w};
#pragma unroll
                for (int j = 0; j < 4; j++)
#pragma unroll
                    for (int i = 0; i < 4; i++) o[j][i] = fmaf(pr[j][kk], va[i], o[j][i]);
            }
        }
    }

    // ---- epilogue: normalize and write out[n][c][q] ----
    float inv[4];
#pragma unroll
    for (int j = 0; j < 4; j++) inv[j] = 1.0f / l[j];
#pragma unroll
    for (int i = 0; i < 4; i++) {
        int c = tx * 4 + i;
        float* orow = out + (size_t)n * CDIM * HW + (size_t)c * HW + q0;
#pragma unroll
        for (int j = 0; j < 4; j++)
            orow[ty * 4 + j] = o[j][i] * inv[j];
    }
}

extern "C" void kernel_launch(void* const* d_in, const int* in_sizes, int n_in,
                              void* d_out, int out_size) {
    const float* X = (const float*)d_in[0];
    float* out = (float*)d_out;
    dim3 grid(HW / BM, NB);
    attn_kernel<<<grid, 256>>>(X, out);
}

// round 3
// speedup vs baseline: 3.2838x; 3.2838x over previous
#include <cuda_runtime.h>
#include <cuda_bf16.h>
#include <cstdint>

#define HW 4096
#define CD 64
#define BM 64
#define BN 64
#define NT (HW / BN)
#define NB 8
#define RB 72  // padded row length in bf16 elems (144B) -> conflict-free ldmatrix

__device__ float g_norms[NB * HW];
__device__ unsigned int g_maxbits[NB];

__device__ __forceinline__ uint32_t smem_u32(const void* p) {
    uint32_t a;
    asm("{ .reg .u64 t; cvta.to.shared.u64 t, %1; cvt.u32.u64 %0, t; }" : "=r"(a) : "l"(p));
    return a;
}
__device__ __forceinline__ void ldsm4(uint32_t addr, uint32_t* r) {
    asm volatile("ldmatrix.sync.aligned.m8n8.x4.shared.b16 {%0,%1,%2,%3}, [%4];"
                 : "=r"(r[0]), "=r"(r[1]), "=r"(r[2]), "=r"(r[3]) : "r"(addr));
}
__device__ __forceinline__ void ldsm4t(uint32_t addr, uint32_t* r) {
    asm volatile("ldmatrix.sync.aligned.m8n8.x4.trans.shared.b16 {%0,%1,%2,%3}, [%4];"
                 : "=r"(r[0]), "=r"(r[1]), "=r"(r[2]), "=r"(r[3]) : "r"(addr));
}
__device__ __forceinline__ void mma16816(float* d, const uint32_t* a, uint32_t b0, uint32_t b1) {
    asm volatile(
        "mma.sync.aligned.m16n8k16.row.col.f32.bf16.bf16.f32 "
        "{%0,%1,%2,%3}, {%4,%5,%6,%7}, {%8,%9}, {%0,%1,%2,%3};"
        : "+f"(d[0]), "+f"(d[1]), "+f"(d[2]), "+f"(d[3])
        : "r"(a[0]), "r"(a[1]), "r"(a[2]), "r"(a[3]), "r"(b0), "r"(b1));
}
__device__ __forceinline__ uint32_t pk2(__nv_bfloat16 a, __nv_bfloat16 b) {
    return (uint32_t)__bfloat16_as_ushort(a) | ((uint32_t)__bfloat16_as_ushort(b) << 16);
}
// split two floats into packed bf16 hi + bf16 lo (residual)
__device__ __forceinline__ void split2(float x, float y, uint32_t& hi, uint32_t& lo) {
    __nv_bfloat16 hx = __float2bfloat16_rn(x), hy = __float2bfloat16_rn(y);
    __nv_bfloat16 lx = __float2bfloat16_rn(x - __bfloat162float(hx));
    __nv_bfloat16 ly = __float2bfloat16_rn(y - __bfloat162float(hy));
    hi = pk2(hx, hy);
    lo = pk2(lx, ly);
}

// ---------------- norm pre-kernel: row norms + per-batch max ----------------
__global__ __launch_bounds__(256) void norm_kernel(const float* __restrict__ X) {
    const int n = blockIdx.y;
    const int q = blockIdx.x * 256 + threadIdx.x;
    const float* Xn = X + (size_t)n * CD * HW;
    float s = 0.f;
#pragma unroll
    for (int c = 0; c < CD; c++) {
        float v = Xn[c * HW + q];
        s = fmaf(v, v, s);
    }
    float nr = sqrtf(s);
    g_norms[n * HW + q] = nr;
    __shared__ float red[8];
    float m = nr;
#pragma unroll
    for (int w = 16; w; w >>= 1) m = fmaxf(m, __shfl_xor_sync(~0u, m, w));
    if ((threadIdx.x & 31) == 0) red[threadIdx.x >> 5] = m;
    __syncthreads();
    if (threadIdx.x < 8) {
        float mm = red[threadIdx.x];
#pragma unroll
        for (int w = 4; w; w >>= 1) mm = fmaxf(mm, __shfl_xor_sync(0xffu, mm, w));
        if (threadIdx.x == 0) atomicMax(&g_maxbits[n], __float_as_uint(mm));
    }
}

// ---------------- main attention kernel (mma.sync bf16 3-pass) ----------------
__global__ __launch_bounds__(256) void attn_mma(const float* __restrict__ X,
                                                float* __restrict__ out) {
    // smem: QH | QL | VH | VL, each 64 x 72 bf16 = 9216B. total 36864B.
    __shared__ __align__(1024) char SM[36864];
    const int QHo = 0, QLo = 9216, VHo = 18432, VLo = 27648;
    const uint32_t smb = smem_u32(SM);

    const int n = blockIdx.y;
    const int q0 = blockIdx.x * BM;
    const int tid = threadIdx.x;
    const int lane = tid & 31;
    const int wid = tid >> 5;
    const int wr = wid >> 1;   // q-row group (0..3): rows wr*16..wr*16+15
    const int wc = wid & 1;    // key-col group (0..1): keys wc*32..wc*32+31
    const int g = lane >> 2, tq = lane & 3;
    const int r8 = lane & 7, sel = lane >> 3;
    const float* Xn = X + (size_t)n * CD * HW;

    // ---- stage Q tile [q][c] hi/lo ----
#pragma unroll
    for (int i = 0; i < 4; i++) {
        int idx = i * 256 + tid;
        int c = idx >> 4, q4 = idx & 15;
        float4 v = *(const float4*)(Xn + c * HW + q0 + q4 * 4);
        float vv[4] = {v.x, v.y, v.z, v.w};
#pragma unroll
        for (int e = 0; e < 4; e++) {
            int q = q4 * 4 + e;
            __nv_bfloat16 h = __float2bfloat16_rn(vv[e]);
            __nv_bfloat16 l = __float2bfloat16_rn(vv[e] - __bfloat162float(h));
            *(ushort*)(SM + QHo + (q * RB + c) * 2) = __bfloat16_as_ushort(h);
            *(ushort*)(SM + QLo + (q * RB + c) * 2) = __bfloat16_as_ushort(l);
        }
    }
    __syncthreads();

    // ---- Q A-fragments into registers (4 c-chunks, hi+lo) ----
    uint32_t qh[4][4], ql[4][4];
    {
        int row = wr * 16 + (sel & 1) * 8 + r8;
#pragma unroll
        for (int ch = 0; ch < 4; ch++) {
            int col = ch * 16 + (sel >> 1) * 8;
            ldsm4(smb + QHo + (row * RB + col) * 2, qh[ch]);
            ldsm4(smb + QLo + (row * RB + col) * 2, ql[ch]);
        }
    }

    const float mxn = __uint_as_float(g_maxbits[n]);
    const int row_a = wr * 16 + g, row_b = row_a + 8;
    const float Ma = g_norms[n * HW + q0 + row_a] * mxn;
    const float Mb = g_norms[n * HW + q0 + row_b] * mxn;

    float o[8][4];
#pragma unroll
    for (int j = 0; j < 8; j++)
#pragma unroll
        for (int r = 0; r < 4; r++) o[j][r] = 0.f;
    float la = 0.f, lb = 0.f;

    // per-lane ldsm byte offsets (within VH/VL), modulo loop indices
    const uint32_t g1off = ((sel & 1) * 8 + r8) * (RB * 2) + (wc * 32 + (sel >> 1) * 8) * 2;
    const uint32_t g2off = ((sel >> 1) * 8 + r8) * (RB * 2) + (wc * 32 + (sel & 1) * 8) * 2;

    for (int t = 0; t < NT; t++) {
        __syncthreads();  // previous tile's ldsm reads complete
        const int kb = t * BN;
        // ---- load KV tile -> [c][key] hi/lo ----
#pragma unroll
        for (int i = 0; i < 4; i++) {
            int idx = i * 256 + tid;
            int c = idx >> 4, k4 = idx & 15;
            float4 v = *(const float4*)(Xn + c * HW + kb + k4 * 4);
            uint32_t h0, l0, h1, l1;
            split2(v.x, v.y, h0, l0);
            split2(v.z, v.w, h1, l1);
            *(uint2*)(SM + VHo + (c * RB + k4 * 4) * 2) = make_uint2(h0, h1);
            *(uint2*)(SM + VLo + (c * RB + k4 * 4) * 2) = make_uint2(l0, l1);
        }
        __syncthreads();

        // ---- gemm1: S = Q Kt (3 split passes) ----
        float s[4][4];
#pragma unroll
        for (int j = 0; j < 4; j++)
#pragma unroll
            for (int r = 0; r < 4; r++) s[j][r] = 0.f;
#pragma unroll
        for (int jp = 0; jp < 2; jp++) {
#pragma unroll
            for (int ch = 0; ch < 4; ch++) {
                uint32_t off = g1off + ch * 16 * (RB * 2) + jp * 32;  // +16 keys = 32B
                uint32_t bh[4], bl[4];
                ldsm4t(smb + VHo + off, bh);
                ldsm4t(smb + VLo + off, bl);
                mma16816(s[2 * jp], qh[ch], bh[0], bh[1]);
                mma16816(s[2 * jp + 1], qh[ch], bh[2], bh[3]);
                mma16816(s[2 * jp], qh[ch], bl[0], bl[1]);
                mma16816(s[2 * jp + 1], qh[ch], bl[2], bl[3]);
                mma16816(s[2 * jp], ql[ch], bh[0], bh[1]);
                mma16816(s[2 * jp + 1], ql[ch], bh[2], bh[3]);
            }
        }

        // ---- softmax (static shift, no rescale) + P pack ----
        uint32_t ph[2][4], pl[2][4];
#pragma unroll
        for (int j = 0; j < 4; j++) {
            float e0 = __expf(s[j][0] - Ma), e1 = __expf(s[j][1] - Ma);
            float e2 = __expf(s[j][2] - Mb), e3 = __expf(s[j][3] - Mb);
            la += e0 + e1;
            lb += e2 + e3;
            int kc = j >> 1, h = j & 1;
            split2(e0, e1, ph[kc][h * 2], pl[kc][h * 2]);
            split2(e2, e3, ph[kc][h * 2 + 1], pl[kc][h * 2 + 1]);
        }

        // ---- gemm2: O += P V (P from regs, 3 split passes) ----
#pragma unroll
        for (int nt = 0; nt < 4; nt++) {
#pragma unroll
            for (int kc = 0; kc < 2; kc++) {
                uint32_t off = g2off + nt * 16 * (RB * 2) + kc * 32;
                uint32_t bh[4], bl[4];
                ldsm4(smb + VHo + off, bh);
                ldsm4(smb + VLo + off, bl);
                mma16816(o[2 * nt], ph[kc], bh[0], bh[1]);
                mma16816(o[2 * nt + 1], ph[kc], bh[2], bh[3]);
                mma16816(o[2 * nt], ph[kc], bl[0], bl[1]);
                mma16816(o[2 * nt + 1], ph[kc], bl[2], bl[3]);
                mma16816(o[2 * nt], pl[kc], bh[0], bh[1]);
                mma16816(o[2 * nt + 1], pl[kc], bh[2], bh[3]);
            }
        }
    }

    // ---- epilogue: cross-warp (wc) reduction of O and l, normalize, store ----
    __syncthreads();
    float* Osm = (float*)SM;             // [64][72] f32 (reuses Q region)
    float* Lsm = (float*)(SM + VHo);     // [64][2]
    la += __shfl_xor_sync(~0u, la, 1);
    la += __shfl_xor_sync(~0u, la, 2);
    lb += __shfl_xor_sync(~0u, lb, 1);
    lb += __shfl_xor_sync(~0u, lb, 2);
    if (tq == 0) {
        Lsm[row_a * 2 + wc] = la;
        Lsm[row_b * 2 + wc] = lb;
    }
    if (wc == 0) {
#pragma unroll
        for (int j = 0; j < 8; j++) {
            int cb = j * 8 + 2 * tq;
            Osm[row_a * RB + cb] = o[j][0];
            Osm[row_a * RB + cb + 1] = o[j][1];
            Osm[row_b * RB + cb] = o[j][2];
            Osm[row_b * RB + cb + 1] = o[j][3];
        }
    }
    __syncthreads();
    if (wc == 1) {
        float ia = 1.f / (Lsm[row_a * 2] + Lsm[row_a * 2 + 1]);
        float ib = 1.f / (Lsm[row_b * 2] + Lsm[row_b * 2 + 1]);
        float* On = out + (size_t)n * CD * HW + q0;
#pragma unroll
        for (int j = 0; j < 8; j++) {
            int cb = j * 8 + 2 * tq;
            On[(size_t)cb * HW + row_a] = (o[j][0] + Osm[row_a * RB + cb]) * ia;
            On[(size_t)(cb + 1) * HW + row_a] = (o[j][1] + Osm[row_a * RB + cb + 1]) * ia;
            On[(size_t)cb * HW + row_b] = (o[j][2] + Osm[row_b * RB + cb]) * ib;
            On[(size_t)(cb + 1) * HW + row_b] = (o[j][3] + Osm[row_b * RB + cb + 1]) * ib;
        }
    }
}

extern "C" void kernel_launch(void* const* d_in, const int* in_sizes, int n_in,
                              void* d_out, int out_size) {
    const float* X = (const float*)d_in[0];
    float* out = (float*)d_out;
    norm_kernel<<<dim3(HW / 256, NB), 256>>>(X);
    attn_mma<<<dim3(HW / BM, NB), 256>>>(X, out);
}

// round 4
// speedup vs baseline: 3.6443x; 1.1098x over previous
#include <cuda_runtime.h>
#include <cuda_bf16.h>
#include <cstdint>

#define HW 4096
#define CD 64
#define BM 64
#define BN 64
#define NT (HW / BN)
#define NB 8
#define RB 72                    // padded row length (bf16 elems) -> conflict-free ldmatrix
#define RBB (RB * 2)             // row bytes = 144
#define HALF_BYTES (64 * RBB)    // one hi or lo tile = 9216B
#define BUF_BYTES (2 * HALF_BYTES)  // hi+lo = 18432B

__device__ __align__(16) __nv_bfloat16 g_XH[NB * CD * HW];
__device__ __align__(16) __nv_bfloat16 g_XL[NB * CD * HW];
__device__ float g_norms[NB * HW];
__device__ unsigned int g_maxbits[NB];

__device__ __forceinline__ uint32_t smem_u32(const void* p) {
    uint32_t a;
    asm("{ .reg .u64 t; cvta.to.shared.u64 t, %1; cvt.u32.u64 %0, t; }" : "=r"(a) : "l"(p));
    return a;
}
__device__ __forceinline__ void ldsm4(uint32_t addr, uint32_t* r) {
    asm volatile("ldmatrix.sync.aligned.m8n8.x4.shared.b16 {%0,%1,%2,%3}, [%4];"
                 : "=r"(r[0]), "=r"(r[1]), "=r"(r[2]), "=r"(r[3]) : "r"(addr));
}
__device__ __forceinline__ void ldsm4t(uint32_t addr, uint32_t* r) {
    asm volatile("ldmatrix.sync.aligned.m8n8.x4.trans.shared.b16 {%0,%1,%2,%3}, [%4];"
                 : "=r"(r[0]), "=r"(r[1]), "=r"(r[2]), "=r"(r[3]) : "r"(addr));
}
__device__ __forceinline__ void mma16816(float* d, const uint32_t* a, uint32_t b0, uint32_t b1) {
    asm volatile(
        "mma.sync.aligned.m16n8k16.row.col.f32.bf16.bf16.f32 "
        "{%0,%1,%2,%3}, {%4,%5,%6,%7}, {%8,%9}, {%0,%1,%2,%3};"
        : "+f"(d[0]), "+f"(d[1]), "+f"(d[2]), "+f"(d[3])
        : "r"(a[0]), "r"(a[1]), "r"(a[2]), "r"(a[3]), "r"(b0), "r"(b1));
}
#define CP16(dst, src) asm volatile("cp.async.cg.shared.global [%0], [%1], 16;" :: "r"(dst), "l"(src))
#define CP_COMMIT()    asm volatile("cp.async.commit_group;" ::: "memory")
#define CP_WAIT1()     asm volatile("cp.async.wait_group 1;" ::: "memory")

__device__ __forceinline__ uint32_t pk2(__nv_bfloat16 a, __nv_bfloat16 b) {
    return (uint32_t)__bfloat16_as_ushort(a) | ((uint32_t)__bfloat16_as_ushort(b) << 16);
}
__device__ __forceinline__ void split2(float x, float y, uint32_t& hi, uint32_t& lo) {
    __nv_bfloat16 hx = __float2bfloat16_rn(x), hy = __float2bfloat16_rn(y);
    __nv_bfloat16 lx = __float2bfloat16_rn(x - __bfloat162float(hx));
    __nv_bfloat16 ly = __float2bfloat16_rn(y - __bfloat162float(hy));
    hi = pk2(hx, hy);
    lo = pk2(lx, ly);
}

// ---------------- pre-kernel 1: split X into bf16 hi/lo global arrays ----------------
__global__ __launch_bounds__(256) void convert_kernel(const float* __restrict__ X) {
    size_t i = (size_t)blockIdx.x * 256 + threadIdx.x;
    float4 v = reinterpret_cast<const float4*>(X)[i];
    uint2 h, l;
    split2(v.x, v.y, h.x, l.x);
    split2(v.z, v.w, h.y, l.y);
    reinterpret_cast<uint2*>(g_XH)[i] = h;
    reinterpret_cast<uint2*>(g_XL)[i] = l;
}

// ---------------- pre-kernel 2: row norms + per-batch max norm ----------------
__global__ __launch_bounds__(256) void norm_kernel(const float* __restrict__ X) {
    const int n = blockIdx.y;
    const int q = blockIdx.x * 256 + threadIdx.x;
    const float* Xn = X + (size_t)n * CD * HW;
    float s = 0.f;
#pragma unroll
    for (int c = 0; c < CD; c++) {
        float v = Xn[c * HW + q];
        s = fmaf(v, v, s);
    }
    float nr = sqrtf(s);
    g_norms[n * HW + q] = nr;
    __shared__ float red[8];
    float m = nr;
#pragma unroll
    for (int w = 16; w; w >>= 1) m = fmaxf(m, __shfl_xor_sync(~0u, m, w));
    if ((threadIdx.x & 31) == 0) red[threadIdx.x >> 5] = m;
    __syncthreads();
    if (threadIdx.x < 8) {
        float mm = red[threadIdx.x];
#pragma unroll
        for (int w = 4; w; w >>= 1) mm = fmaxf(mm, __shfl_xor_sync(0xffu, mm, w));
        if (threadIdx.x == 0) atomicMax(&g_maxbits[n], __float_as_uint(mm));
    }
}

// ---------------- main attention kernel ----------------
__global__ __launch_bounds__(256) void attn_mma(float* __restrict__ out) {
    __shared__ __align__(1024) char SM[2 * BUF_BYTES];  // 36864B: two hi/lo tile buffers
    const uint32_t smb = smem_u32(SM);

    const int n = blockIdx.y;
    const int q0 = blockIdx.x * BM;
    const int tid = threadIdx.x;
    const int lane = tid & 31;
    const int wid = tid >> 5;
    const int wr = wid >> 1;   // q-row group (0..3)
    const int wc = wid & 1;    // key-col group (0..1)
    const int g = lane >> 2, tq = lane & 3;
    const int r8 = lane & 7, sel = lane >> 3;

    const __nv_bfloat16* XHn = g_XH + (size_t)n * CD * HW;
    const __nv_bfloat16* XLn = g_XL + (size_t)n * CD * HW;

    // cp.async one hi/lo tile ([c][64] rows, 128B payload per row, RBB-padded) to smem
    auto stage = [&](uint32_t bufoff, int col0) {
#pragma unroll
        for (int i = 0; i < 4; i++) {
            int idx = i * 256 + tid;
            int half = idx >> 9;
            int c = (idx >> 3) & 63;
            int ch = idx & 7;
            const __nv_bfloat16* src = (half ? XLn : XHn) + c * HW + col0 + ch * 8;
            uint32_t dst = smb + bufoff + half * HALF_BYTES + c * RBB + ch * 16;
            CP16(dst, src);
        }
    };

    stage(BUF_BYTES, q0);  // Q tile -> buf1
    CP_COMMIT();
    stage(0, 0);           // KV tile 0 -> buf0
    CP_COMMIT();
    CP_WAIT1();            // Q done
    __syncthreads();

    // ---- Q A-fragments (trans ldmatrix from [c][q] layout) ----
    uint32_t qh[4][4], ql[4][4];
    {
        const uint32_t qb = smb + BUF_BYTES;
        const uint32_t lo = ((sel >> 1) * 8 + r8) * RBB + (wr * 16 + (sel & 1) * 8) * 2;
#pragma unroll
        for (int ch = 0; ch < 4; ch++) {
            ldsm4t(qb + ch * 16 * RBB + lo, qh[ch]);
            ldsm4t(qb + HALF_BYTES + ch * 16 * RBB + lo, ql[ch]);
        }
    }
    __syncthreads();       // everyone done reading buf1
    stage(BUF_BYTES, BN);  // KV tile 1 -> buf1
    CP_COMMIT();

    const float mxn = __uint_as_float(g_maxbits[n]);
    const int row_a = wr * 16 + g, row_b = row_a + 8;
    const float Ma = g_norms[n * HW + q0 + row_a] * mxn;
    const float Mb = g_norms[n * HW + q0 + row_b] * mxn;

    float o[8][4];
#pragma unroll
    for (int j = 0; j < 8; j++)
#pragma unroll
        for (int r = 0; r < 4; r++) o[j][r] = 0.f;
    float la = 0.f, lb = 0.f;

    const uint32_t g1off = ((sel & 1) * 8 + r8) * RBB + (wc * 32 + (sel >> 1) * 8) * 2;
    const uint32_t g2off = ((sel >> 1) * 8 + r8) * RBB + (wc * 32 + (sel & 1) * 8) * 2;

    for (int t = 0; t < NT; t++) {
        CP_WAIT1();        // tile t resident
        __syncthreads();
        const uint32_t vb = smb + (t & 1) * BUF_BYTES;

        // ---- gemm1: S = Q Kt (3 split passes: hh + hl + lh) ----
        float s[4][4];
#pragma unroll
        for (int j = 0; j < 4; j++)
#pragma unroll
            for (int r = 0; r < 4; r++) s[j][r] = 0.f;
#pragma unroll
        for (int jp = 0; jp < 2; jp++) {
#pragma unroll
            for (int ch = 0; ch < 4; ch++) {
                uint32_t off = vb + g1off + ch * 16 * RBB + jp * 32;
                uint32_t bh[4], bl[4];
                ldsm4t(off, bh);
                ldsm4t(off + HALF_BYTES, bl);
                mma16816(s[2 * jp], qh[ch], bh[0], bh[1]);
                mma16816(s[2 * jp + 1], qh[ch], bh[2], bh[3]);
                mma16816(s[2 * jp], qh[ch], bl[0], bl[1]);
                mma16816(s[2 * jp + 1], qh[ch], bl[2], bl[3]);
                mma16816(s[2 * jp], ql[ch], bh[0], bh[1]);
                mma16816(s[2 * jp + 1], ql[ch], bh[2], bh[3]);
            }
        }

        // ---- softmax (static norm-based shift, no rescale) + P pack ----
        uint32_t ph[2][4], pl[2][4];
#pragma unroll
        for (int j = 0; j < 4; j++) {
            float e0 = __expf(s[j][0] - Ma), e1 = __expf(s[j][1] - Ma);
            float e2 = __expf(s[j][2] - Mb), e3 = __expf(s[j][3] - Mb);
            la += e0 + e1;
            lb += e2 + e3;
            int kc = j >> 1, h = j & 1;
            split2(e0, e1, ph[kc][h * 2], pl[kc][h * 2]);
            split2(e2, e3, ph[kc][h * 2 + 1], pl[kc][h * 2 + 1]);
        }

        // ---- gemm2: O += P V (P in regs, 3 split passes) ----
#pragma unroll
        for (int nt = 0; nt < 4; nt++) {
#pragma unroll
            for (int kc = 0; kc < 2; kc++) {
                uint32_t off = vb + g2off + nt * 16 * RBB + kc * 32;
                uint32_t bh[4], bl[4];
                ldsm4(off, bh);
                ldsm4(off + HALF_BYTES, bl);
                mma16816(o[2 * nt], ph[kc], bh[0], bh[1]);
                mma16816(o[2 * nt + 1], ph[kc], bh[2], bh[3]);
                mma16816(o[2 * nt], ph[kc], bl[0], bl[1]);
                mma16816(o[2 * nt + 1], ph[kc], bl[2], bl[3]);
                mma16816(o[2 * nt], pl[kc], bh[0], bh[1]);
                mma16816(o[2 * nt + 1], pl[kc], bh[2], bh[3]);
            }
        }
        __syncthreads();   // all reads of buf[t&1] done
        if (t + 2 < NT) stage((t & 1) * BUF_BYTES, (t + 2) * BN);
        CP_COMMIT();       // empty groups in the tail keep wait_group accounting simple
    }

    // ---- epilogue: cross-warp (wc) reduction, normalize, coalesced-ish store ----
    __syncthreads();
    float* Osm = (float*)SM;                 // [64][RB] f32 in buf0
    float* Lsm = (float*)(SM + BUF_BYTES);   // [64][2] in buf1
    la += __shfl_xor_sync(~0u, la, 1);
    la += __shfl_xor_sync(~0u, la, 2);
    lb += __shfl_xor_sync(~0u, lb, 1);
    lb += __shfl_xor_sync(~0u, lb, 2);
    if (tq == 0) {
        Lsm[row_a * 2 + wc] = la;
        Lsm[row_b * 2 + wc] = lb;
    }
    if (wc == 0) {
#pragma unroll
        for (int j = 0; j < 8; j++) {
            int cb = j * 8 + 2 * tq;
            Osm[row_a * RB + cb] = o[j][0];
            Osm[row_a * RB + cb + 1] = o[j][1];
            Osm[row_b * RB + cb] = o[j][2];
            Osm[row_b * RB + cb + 1] = o[j][3];
        }
    }
    __syncthreads();
    if (wc == 1) {
        float ia = 1.f / (Lsm[row_a * 2] + Lsm[row_a * 2 + 1]);
        float ib = 1.f / (Lsm[row_b * 2] + Lsm[row_b * 2 + 1]);
        float* On = out + (size_t)n * CD * HW + q0;
#pragma unroll
        for (int j = 0; j < 8; j++) {
            int cb = j * 8 + 2 * tq;
            On[(size_t)cb * HW + row_a] = (o[j][0] + Osm[row_a * RB + cb]) * ia;
            On[(size_t)(cb + 1) * HW + row_a] = (o[j][1] + Osm[row_a * RB + cb + 1]) * ia;
            On[(size_t)cb * HW + row_b] = (o[j][2] + Osm[row_b * RB + cb]) * ib;
            On[(size_t)(cb + 1) * HW + row_b] = (o[j][3] + Osm[row_b * RB + cb + 1]) * ib;
        }
    }
}

extern "C" void kernel_launch(void* const* d_in, const int* in_sizes, int n_in,
                              void* d_out, int out_size) {
    const float* X = (const float*)d_in[0];
    float* out = (float*)d_out;
    convert_kernel<<<(NB * CD * HW / 4) / 256, 256>>>(X);
    norm_kernel<<<dim3(HW / 256, NB), 256>>>(X);
    attn_mma<<<dim3(HW / BM, NB), 256>>>(out);
}

// round 5
// speedup vs baseline: 3.8203x; 1.0483x over previous
#include <cuda_runtime.h>
#include <cuda_bf16.h>
#include <cstdint>

#define HW 4096
#define CD 64
#define BM 64
#define BN 64
#define NT (HW / BN)
#define NB 8
#define RB 72                    // padded row length (bf16 elems) -> conflict-free ldmatrix
#define RBB (RB * 2)             // row bytes = 144
#define HALF_BYTES (64 * RBB)    // one hi or lo tile = 9216B
#define BUF_BYTES (2 * HALF_BYTES)  // hi+lo = 18432B

__device__ __align__(16) __nv_bfloat16 g_XH[NB * CD * HW];
__device__ __align__(16) __nv_bfloat16 g_XL[NB * CD * HW];
__device__ float g_norms[NB * HW];
__device__ unsigned int g_maxbits[NB];

__device__ __forceinline__ uint32_t smem_u32(const void* p) {
    uint32_t a;
    asm("{ .reg .u64 t; cvta.to.shared.u64 t, %1; cvt.u32.u64 %0, t; }" : "=r"(a) : "l"(p));
    return a;
}
__device__ __forceinline__ void ldsm4(uint32_t addr, uint32_t* r) {
    asm volatile("ldmatrix.sync.aligned.m8n8.x4.shared.b16 {%0,%1,%2,%3}, [%4];"
                 : "=r"(r[0]), "=r"(r[1]), "=r"(r[2]), "=r"(r[3]) : "r"(addr));
}
__device__ __forceinline__ void ldsm4t(uint32_t addr, uint32_t* r) {
    asm volatile("ldmatrix.sync.aligned.m8n8.x4.trans.shared.b16 {%0,%1,%2,%3}, [%4];"
                 : "=r"(r[0]), "=r"(r[1]), "=r"(r[2]), "=r"(r[3]) : "r"(addr));
}
__device__ __forceinline__ void mma16816(float* d, const uint32_t* a, uint32_t b0, uint32_t b1) {
    asm volatile(
        "mma.sync.aligned.m16n8k16.row.col.f32.bf16.bf16.f32 "
        "{%0,%1,%2,%3}, {%4,%5,%6,%7}, {%8,%9}, {%0,%1,%2,%3};"
        : "+f"(d[0]), "+f"(d[1]), "+f"(d[2]), "+f"(d[3])
        : "r"(a[0]), "r"(a[1]), "r"(a[2]), "r"(a[3]), "r"(b0), "r"(b1));
}
#define CP16(dst, src) asm volatile("cp.async.cg.shared.global [%0], [%1], 16;" :: "r"(dst), "l"(src))
#define CP_COMMIT()    asm volatile("cp.async.commit_group;" ::: "memory")
#define CP_WAIT1()     asm volatile("cp.async.wait_group 1;" ::: "memory")

__device__ __forceinline__ uint32_t pk2(__nv_bfloat16 a, __nv_bfloat16 b) {
    return (uint32_t)__bfloat16_as_ushort(a) | ((uint32_t)__bfloat16_as_ushort(b) << 16);
}
__device__ __forceinline__ void split2(float x, float y, uint32_t& hi, uint32_t& lo) {
    __nv_bfloat16 hx = __float2bfloat16_rn(x), hy = __float2bfloat16_rn(y);
    __nv_bfloat16 lx = __float2bfloat16_rn(x - __bfloat162float(hx));
    __nv_bfloat16 ly = __float2bfloat16_rn(y - __bfloat162float(hy));
    hi = pk2(hx, hy);
    lo = pk2(lx, ly);
}

// ---------------- pre-kernel 1: split X into bf16 hi/lo global arrays ----------------
__global__ __launch_bounds__(256) void convert_kernel(const float* __restrict__ X) {
    size_t i = (size_t)blockIdx.x * 256 + threadIdx.x;
    float4 v = reinterpret_cast<const float4*>(X)[i];
    uint2 h, l;
    split2(v.x, v.y, h.x, l.x);
    split2(v.z, v.w, h.y, l.y);
    reinterpret_cast<uint2*>(g_XH)[i] = h;
    reinterpret_cast<uint2*>(g_XL)[i] = l;
}

// ---------------- pre-kernel 2: row norms + per-batch max norm ----------------
__global__ __launch_bounds__(256) void norm_kernel(const float* __restrict__ X) {
    const int n = blockIdx.y;
    const int q = blockIdx.x * 256 + threadIdx.x;
    const float* Xn = X + (size_t)n * CD * HW;
    float s = 0.f;
#pragma unroll
    for (int c = 0; c < CD; c++) {
        float v = Xn[c * HW + q];
        s = fmaf(v, v, s);
    }
    float nr = sqrtf(s);
    g_norms[n * HW + q] = nr;
    __shared__ float red[8];
    float m = nr;
#pragma unroll
    for (int w = 16; w; w >>= 1) m = fmaxf(m, __shfl_xor_sync(~0u, m, w));
    if ((threadIdx.x & 31) == 0) red[threadIdx.x >> 5] = m;
    __syncthreads();
    if (threadIdx.x < 8) {
        float mm = red[threadIdx.x];
#pragma unroll
        for (int w = 4; w; w >>= 1) mm = fmaxf(mm, __shfl_xor_sync(0xffu, mm, w));
        if (threadIdx.x == 0) atomicMax(&g_maxbits[n], __float_as_uint(mm));
    }
}

// ---------------- main attention kernel ----------------
__global__ __launch_bounds__(256, 2) void attn_mma(float* __restrict__ out) {
    __shared__ __align__(1024) char SM[2 * BUF_BYTES];  // 36864B: two hi/lo tile buffers
    const uint32_t smb = smem_u32(SM);

    const int n = blockIdx.y;
    const int q0 = blockIdx.x * BM;
    const int tid = threadIdx.x;
    const int lane = tid & 31;
    const int wid = tid >> 5;
    const int wr = wid >> 1;   // q-row group (0..3)
    const int wc = wid & 1;    // key-col group (0..1)
    const int g = lane >> 2, tq = lane & 3;
    const int r8 = lane & 7, sel = lane >> 3;

    const __nv_bfloat16* XHn = g_XH + (size_t)n * CD * HW;
    const __nv_bfloat16* XLn = g_XL + (size_t)n * CD * HW;

    auto stage = [&](uint32_t bufoff, int col0) {
#pragma unroll
        for (int i = 0; i < 4; i++) {
            int idx = i * 256 + tid;
            int half = idx >> 9;
            int c = (idx >> 3) & 63;
            int ch = idx & 7;
            const __nv_bfloat16* src = (half ? XLn : XHn) + c * HW + col0 + ch * 8;
            uint32_t dst = smb + bufoff + half * HALF_BYTES + c * RBB + ch * 16;
            CP16(dst, src);
        }
    };

    stage(BUF_BYTES, q0);  // Q tile -> buf1
    CP_COMMIT();
    stage(0, 0);           // KV tile 0 -> buf0
    CP_COMMIT();
    CP_WAIT1();            // Q done
    __syncthreads();

    // ---- Q A-fragments (trans ldmatrix from [c][q] layout) ----
    uint32_t qh[4][4], ql[4][4];
    {
        const uint32_t qb = smb + BUF_BYTES;
        const uint32_t lo = ((sel >> 1) * 8 + r8) * RBB + (wr * 16 + (sel & 1) * 8) * 2;
#pragma unroll
        for (int ch = 0; ch < 4; ch++) {
            ldsm4t(qb + ch * 16 * RBB + lo, qh[ch]);
            ldsm4t(qb + HALF_BYTES + ch * 16 * RBB + lo, ql[ch]);
        }
    }
    __syncthreads();       // everyone done reading buf1
    stage(BUF_BYTES, BN);  // KV tile 1 -> buf1
    CP_COMMIT();

    const float mxn = __uint_as_float(g_maxbits[n]);
    const int row_a = wr * 16 + g, row_b = row_a + 8;
    const float Ma = g_norms[n * HW + q0 + row_a] * mxn;
    const float Mb = g_norms[n * HW + q0 + row_b] * mxn;

    float o[8][4];
#pragma unroll
    for (int j = 0; j < 8; j++)
#pragma unroll
        for (int r = 0; r < 4; r++) o[j][r] = 0.f;
    float la = 0.f, lb = 0.f;

    const uint32_t g1off = ((sel & 1) * 8 + r8) * RBB + (wc * 32 + (sel >> 1) * 8) * 2;
    const uint32_t g2off = ((sel >> 1) * 8 + r8) * RBB + (wc * 32 + (sel & 1) * 8) * 2;

    for (int t = 0; t < NT; t++) {
        CP_WAIT1();        // tile t resident
        __syncthreads();
        const uint32_t vb = smb + (t & 1) * BUF_BYTES;

        // ---- gemm1: S = Q Kt, 3 split passes, accumulator-interleaved ----
        float s[4][4];
#pragma unroll
        for (int j = 0; j < 4; j++)
#pragma unroll
            for (int r = 0; r < 4; r++) s[j][r] = 0.f;
#pragma unroll
        for (int ch = 0; ch < 4; ch++) {
            const uint32_t base = vb + g1off + ch * 16 * RBB;
            uint32_t bh0[4], bl0[4], bh1[4], bl1[4];
            ldsm4t(base, bh0);
            ldsm4t(base + HALF_BYTES, bl0);
            ldsm4t(base + 32, bh1);
            ldsm4t(base + 32 + HALF_BYTES, bl1);
            // 12 MMAs, round-robin over 4 independent accumulators (gap-4 chains)
            mma16816(s[0], qh[ch], bh0[0], bh0[1]);
            mma16816(s[1], qh[ch], bh0[2], bh0[3]);
            mma16816(s[2], qh[ch], bh1[0], bh1[1]);
            mma16816(s[3], qh[ch], bh1[2], bh1[3]);
            mma16816(s[0], qh[ch], bl0[0], bl0[1]);
            mma16816(s[1], qh[ch], bl0[2], bl0[3]);
            mma16816(s[2], qh[ch], bl1[0], bl1[1]);
            mma16816(s[3], qh[ch], bl1[2], bl1[3]);
            mma16816(s[0], ql[ch], bh0[0], bh0[1]);
            mma16816(s[1], ql[ch], bh0[2], bh0[3]);
            mma16816(s[2], ql[ch], bh1[0], bh1[1]);
            mma16816(s[3], ql[ch], bh1[2], bh1[3]);
        }

        // ---- softmax (static norm-based shift, no rescale) + P pack ----
        uint32_t ph[2][4], pl[2][4];
#pragma unroll
        for (int j = 0; j < 4; j++) {
            float e0 = __expf(s[j][0] - Ma), e1 = __expf(s[j][1] - Ma);
            float e2 = __expf(s[j][2] - Mb), e3 = __expf(s[j][3] - Mb);
            la += e0 + e1;
            lb += e2 + e3;
            int kc = j >> 1, h = j & 1;
            split2(e0, e1, ph[kc][h * 2], pl[kc][h * 2]);
            split2(e2, e3, ph[kc][h * 2 + 1], pl[kc][h * 2 + 1]);
        }

        // ---- gemm2: O += P V, 3 split passes, accumulator-interleaved (nt pairs) ----
#pragma unroll
        for (int m = 0; m < 2; m++) {
#pragma unroll
            for (int kc = 0; kc < 2; kc++) {
                const uint32_t ba = vb + g2off + (2 * m) * 16 * RBB + kc * 32;
                const uint32_t bb = ba + 16 * RBB;
                uint32_t bha[4], bla[4], bhb[4], blb[4];
                ldsm4(ba, bha);
                ldsm4(ba + HALF_BYTES, bla);
                ldsm4(bb, bhb);
                ldsm4(bb + HALF_BYTES, blb);
                float* oa0 = o[4 * m], * oa1 = o[4 * m + 1];
                float* ob0 = o[4 * m + 2], * ob1 = o[4 * m + 3];
                mma16816(oa0, ph[kc], bha[0], bha[1]);
                mma16816(oa1, ph[kc], bha[2], bha[3]);
                mma16816(ob0, ph[kc], bhb[0], bhb[1]);
                mma16816(ob1, ph[kc], bhb[2], bhb[3]);
                mma16816(oa0, ph[kc], bla[0], bla[1]);
                mma16816(oa1, ph[kc], bla[2], bla[3]);
                mma16816(ob0, ph[kc], blb[0], blb[1]);
                mma16816(ob1, ph[kc], blb[2], blb[3]);
                mma16816(oa0, pl[kc], bha[0], bha[1]);
                mma16816(oa1, pl[kc], bha[2], bha[3]);
                mma16816(ob0, pl[kc], bhb[0], bhb[1]);
                mma16816(ob1, pl[kc], bhb[2], bhb[3]);
            }
        }
        __syncthreads();   // all reads of buf[t&1] done
        if (t + 2 < NT) stage((t & 1) * BUF_BYTES, (t + 2) * BN);
        CP_COMMIT();
    }

    // ---- epilogue: cross-warp (wc) reduction, normalize, store ----
    __syncthreads();
    float* Osm = (float*)SM;                 // [64][RB] f32 in buf0
    float* Lsm = (float*)(SM + BUF_BYTES);   // [64][2] in buf1
    la += __shfl_xor_sync(~0u, la, 1);
    la += __shfl_xor_sync(~0u, la, 2);
    lb += __shfl_xor_sync(~0u, lb, 1);
    lb += __shfl_xor_sync(~0u, lb, 2);
    if (tq == 0) {
        Lsm[row_a * 2 + wc] = la;
        Lsm[row_b * 2 + wc] = lb;
    }
    if (wc == 0) {
#pragma unroll
        for (int j = 0; j < 8; j++) {
            int cb = j * 8 + 2 * tq;
            Osm[row_a * RB + cb] = o[j][0];
            Osm[row_a * RB + cb + 1] = o[j][1];
            Osm[row_b * RB + cb] = o[j][2];
            Osm[row_b * RB + cb + 1] = o[j][3];
        }
    }
    __syncthreads();
    if (wc == 1) {
        float ia = 1.f / (Lsm[row_a * 2] + Lsm[row_a * 2 + 1]);
        float ib = 1.f / (Lsm[row_b * 2] + Lsm[row_b * 2 + 1]);
        float* On = out + (size_t)n * CD * HW + q0;
#pragma unroll
        for (int j = 0; j < 8; j++) {
            int cb = j * 8 + 2 * tq;
            On[(size_t)cb * HW + row_a] = (o[j][0] + Osm[row_a * RB + cb]) * ia;
            On[(size_t)(cb + 1) * HW + row_a] = (o[j][1] + Osm[row_a * RB + cb + 1]) * ia;
            On[(size_t)cb * HW + row_b] = (o[j][2] + Osm[row_b * RB + cb]) * ib;
            On[(size_t)(cb + 1) * HW + row_b] = (o[j][3] + Osm[row_b * RB + cb + 1]) * ib;
        }
    }
}

extern "C" void kernel_launch(void* const* d_in, const int* in_sizes, int n_in,
                              void* d_out, int out_size) {
    const float* X = (const float*)d_in[0];
    float* out = (float*)d_out;
    convert_kernel<<<(NB * CD * HW / 4) / 256, 256>>>(X);
    norm_kernel<<<dim3(HW / 256, NB), 256>>>(X);
    attn_mma<<<dim3(HW / BM, NB), 256>>>(out);
}

// round 7
// speedup vs baseline: 4.7088x; 1.2326x over previous
#include <cuda_runtime.h>
#include <cuda_bf16.h>
#include <cuda_fp16.h>
#include <cstdint>

#define HW 4096
#define CD 64
#define BM 64
#define BN 64
#define NT (HW / BN)
#define NB 8
#define RB 72                    // padded row length (16b elems) -> conflict-free ldmatrix
#define RBB (RB * 2)             // row bytes = 144
#define HALF_BYTES (64 * RBB)    // one sub-tile = 9216B
#define BUF_BYTES (3 * HALF_BYTES)  // bf16-hi + bf16-lo + fp16 = 27648B
#define SMEM_TOTAL (2 * BUF_BYTES)  // 55296B

__device__ __align__(16) __nv_bfloat16 g_XH[NB * CD * HW];
__device__ __align__(16) __nv_bfloat16 g_XL[NB * CD * HW];
__device__ __align__(16) __half g_XF[NB * CD * HW];

__device__ __forceinline__ uint32_t smem_u32(const void* p) {
    uint32_t a;
    asm("{ .reg .u64 t; cvta.to.shared.u64 t, %1; cvt.u32.u64 %0, t; }" : "=r"(a) : "l"(p));
    return a;
}
__device__ __forceinline__ void ldsm4(uint32_t addr, uint32_t* r) {
    asm volatile("ldmatrix.sync.aligned.m8n8.x4.shared.b16 {%0,%1,%2,%3}, [%4];"
                 : "=r"(r[0]), "=r"(r[1]), "=r"(r[2]), "=r"(r[3]) : "r"(addr));
}
__device__ __forceinline__ void ldsm4t(uint32_t addr, uint32_t* r) {
    asm volatile("ldmatrix.sync.aligned.m8n8.x4.trans.shared.b16 {%0,%1,%2,%3}, [%4];"
                 : "=r"(r[0]), "=r"(r[1]), "=r"(r[2]), "=r"(r[3]) : "r"(addr));
}
__device__ __forceinline__ void mma_bf16(float* d, const uint32_t* a, uint32_t b0, uint32_t b1) {
    asm volatile(
        "mma.sync.aligned.m16n8k16.row.col.f32.bf16.bf16.f32 "
        "{%0,%1,%2,%3}, {%4,%5,%6,%7}, {%8,%9}, {%0,%1,%2,%3};"
        : "+f"(d[0]), "+f"(d[1]), "+f"(d[2]), "+f"(d[3])
        : "r"(a[0]), "r"(a[1]), "r"(a[2]), "r"(a[3]), "r"(b0), "r"(b1));
}
__device__ __forceinline__ void mma_f16(float* d, const uint32_t* a, uint32_t b0, uint32_t b1) {
    asm volatile(
        "mma.sync.aligned.m16n8k16.row.col.f32.f16.f16.f32 "
        "{%0,%1,%2,%3}, {%4,%5,%6,%7}, {%8,%9}, {%0,%1,%2,%3};"
        : "+f"(d[0]), "+f"(d[1]), "+f"(d[2]), "+f"(d[3])
        : "r"(a[0]), "r"(a[1]), "r"(a[2]), "r"(a[3]), "r"(b0), "r"(b1));
}
#define CP16(dst, src) asm volatile("cp.async.cg.shared.global [%0], [%1], 16;" :: "r"(dst), "l"(src))
#define CP_COMMIT()    asm volatile("cp.async.commit_group;" ::: "memory")
#define CP_WAIT1()     asm volatile("cp.async.wait_group 1;" ::: "memory")

__device__ __forceinline__ uint32_t pk2(__nv_bfloat16 a, __nv_bfloat16 b) {
    return (uint32_t)__bfloat16_as_ushort(a) | ((uint32_t)__bfloat16_as_ushort(b) << 16);
}
__device__ __forceinline__ void split2(float x, float y, uint32_t& hi, uint32_t& lo) {
    __nv_bfloat16 hx = __float2bfloat16_rn(x), hy = __float2bfloat16_rn(y);
    __nv_bfloat16 lx = __float2bfloat16_rn(x - __bfloat162float(hx));
    __nv_bfloat16 ly = __float2bfloat16_rn(y - __bfloat162float(hy));
    hi = pk2(hx, hy);
    lo = pk2(lx, ly);
}
// pack two f32 -> f16x2 with a in the LOW half (matches pk2 ordering)
__device__ __forceinline__ uint32_t pkf16(float a, float b) {
    uint32_t r;
    asm("cvt.rn.f16x2.f32 %0, %1, %2;" : "=r"(r) : "f"(b), "f"(a));
    return r;
}

// ---------------- pre-kernel: split X into bf16 hi/lo + fp16 global arrays ----------------
__global__ __launch_bounds__(256) void convert_kernel(const float* __restrict__ X) {
    size_t i = (size_t)blockIdx.x * 256 + threadIdx.x;
    float4 v = reinterpret_cast<const float4*>(X)[i];
    uint2 h, l;
    split2(v.x, v.y, h.x, l.x);
    split2(v.z, v.w, h.y, l.y);
    reinterpret_cast<uint2*>(g_XH)[i] = h;
    reinterpret_cast<uint2*>(g_XL)[i] = l;
    uint2 f;
    f.x = pkf16(v.x, v.y);
    f.y = pkf16(v.z, v.w);
    reinterpret_cast<uint2*>(g_XF)[i] = f;
}

// ---------------- main attention kernel ----------------
__global__ __launch_bounds__(256, 2) void attn_mma(float* __restrict__ out) {
    extern __shared__ __align__(128) char SM[];
    const uint32_t smb = smem_u32(SM);

    const int n = blockIdx.y;
    const int q0 = blockIdx.x * BM;
    const int tid = threadIdx.x;
    const int lane = tid & 31;
    const int wid = tid >> 5;
    const int wr = wid >> 1;   // q-row group (0..3)
    const int wc = wid & 1;    // key-col group (0..1)
    const int g = lane >> 2, tq = lane & 3;
    const int r8 = lane & 7, sel = lane >> 3;

    const char* XHn = (const char*)(g_XH + (size_t)n * CD * HW);
    const char* XLn = (const char*)(g_XL + (size_t)n * CD * HW);
    const char* XFn = (const char*)(g_XF + (size_t)n * CD * HW);

    auto stageKV = [&](uint32_t bufoff, int col0) {
#pragma unroll
        for (int i = 0; i < 6; i++) {
            int idx = i * 256 + tid;
            int sub = idx >> 9;
            int c = (idx >> 3) & 63;
            int ch = idx & 7;
            const char* base = (sub == 0) ? XHn : (sub == 1) ? XLn : XFn;
            const char* src = base + ((size_t)c * HW + col0 + ch * 8) * 2;
            uint32_t dst = smb + bufoff + sub * HALF_BYTES + c * RBB + ch * 16;
            CP16(dst, src);
        }
    };
    auto stageQ = [&](uint32_t bufoff, int col0) {
#pragma unroll
        for (int i = 0; i < 4; i++) {
            int idx = i * 256 + tid;
            int half = idx >> 9;
            int c = (idx >> 3) & 63;
            int ch = idx & 7;
            const char* base = half ? XLn : XHn;
            const char* src = base + ((size_t)c * HW + col0 + ch * 8) * 2;
            uint32_t dst = smb + bufoff + half * HALF_BYTES + c * RBB + ch * 16;
            CP16(dst, src);
        }
    };

    stageQ(BUF_BYTES, q0);   // Q -> buf1
    CP_COMMIT();
    stageKV(0, 0);           // KV tile 0 -> buf0
    CP_COMMIT();
    CP_WAIT1();              // Q done
    __syncthreads();

    // ---- Q A-fragments (trans ldmatrix from [c][q] layout) ----
    uint32_t qh[4][4], ql[4][4];
    {
        const uint32_t qb = smb + BUF_BYTES;
        const uint32_t lo = ((sel >> 1) * 8 + r8) * RBB + (wr * 16 + (sel & 1) * 8) * 2;
#pragma unroll
        for (int ch = 0; ch < 4; ch++) {
            ldsm4t(qb + ch * 16 * RBB + lo, qh[ch]);
            ldsm4t(qb + HALF_BYTES + ch * 16 * RBB + lo, ql[ch]);
        }
    }
    __syncthreads();         // everyone done reading buf1
    stageKV(BUF_BYTES, BN);  // KV tile 1 -> buf1
    CP_COMMIT();

    const int row_a = wr * 16 + g, row_b = row_a + 8;

    float o[8][4];
#pragma unroll
    for (int j = 0; j < 8; j++)
#pragma unroll
        for (int r = 0; r < 4; r++) o[j][r] = 0.f;
    float la = 0.f, lb = 0.f;
    float ma = -1e30f, mb = -1e30f;  // per-warp-half running row max

    const uint32_t g1off = ((sel & 1) * 8 + r8) * RBB + (wc * 32 + (sel >> 1) * 8) * 2;
    const uint32_t g2off = ((sel >> 1) * 8 + r8) * RBB + (wc * 32 + (sel & 1) * 8) * 2;

    for (int t = 0; t < NT; t++) {
        CP_WAIT1();          // tile t resident
        __syncthreads();
        const uint32_t vb = smb + (t & 1) * BUF_BYTES;

        // ---- gemm1: S = Q Kt, bf16 3 split passes, accumulator-interleaved ----
        float s[4][4];
#pragma unroll
        for (int j = 0; j < 4; j++)
#pragma unroll
            for (int r = 0; r < 4; r++) s[j][r] = 0.f;
#pragma unroll
        for (int ch = 0; ch < 4; ch++) {
            const uint32_t base = vb + g1off + ch * 16 * RBB;
            uint32_t bh0[4], bl0[4], bh1[4], bl1[4];
            ldsm4t(base, bh0);
            ldsm4t(base + HALF_BYTES, bl0);
            ldsm4t(base + 32, bh1);
            ldsm4t(base + 32 + HALF_BYTES, bl1);
            mma_bf16(s[0], qh[ch], bh0[0], bh0[1]);
            mma_bf16(s[1], qh[ch], bh0[2], bh0[3]);
            mma_bf16(s[2], qh[ch], bh1[0], bh1[1]);
            mma_bf16(s[3], qh[ch], bh1[2], bh1[3]);
            mma_bf16(s[0], qh[ch], bl0[0], bl0[1]);
            mma_bf16(s[1], qh[ch], bl0[2], bl0[3]);
            mma_bf16(s[2], qh[ch], bl1[0], bl1[1]);
            mma_bf16(s[3], qh[ch], bl1[2], bl1[3]);
            mma_bf16(s[0], ql[ch], bh0[0], bh0[1]);
            mma_bf16(s[1], ql[ch], bh0[2], bh0[3]);
            mma_bf16(s[2], ql[ch], bh1[0], bh1[1]);
            mma_bf16(s[3], ql[ch], bh1[2], bh1[3]);
        }

        // ---- online softmax (FA2, per warp-half) ----
        float am = fmaxf(fmaxf(s[0][0], s[0][1]), fmaxf(s[1][0], s[1][1]));
        am = fmaxf(am, fmaxf(fmaxf(s[2][0], s[2][1]), fmaxf(s[3][0], s[3][1])));
        float bm = fmaxf(fmaxf(s[0][2], s[0][3]), fmaxf(s[1][2], s[1][3]));
        bm = fmaxf(bm, fmaxf(fmaxf(s[2][2], s[2][3]), fmaxf(s[3][2], s[3][3])));
        am = fmaxf(am, __shfl_xor_sync(~0u, am, 1));
        am = fmaxf(am, __shfl_xor_sync(~0u, am, 2));
        bm = fmaxf(bm, __shfl_xor_sync(~0u, bm, 1));
        bm = fmaxf(bm, __shfl_xor_sync(~0u, bm, 2));
        float man = fmaxf(ma, am), mbn = fmaxf(mb, bm);
        float ca = __expf(ma - man), cb = __expf(mb - mbn);
        ma = man;
        mb = mbn;
        la *= ca;
        lb *= cb;
#pragma unroll
        for (int j = 0; j < 8; j++) {
            o[j][0] *= ca;
            o[j][1] *= ca;
            o[j][2] *= cb;
            o[j][3] *= cb;
        }

        uint32_t pf[2][4];
#pragma unroll
        for (int j = 0; j < 4; j++) {
            float e0 = __expf(s[j][0] - ma), e1 = __expf(s[j][1] - ma);
            float e2 = __expf(s[j][2] - mb), e3 = __expf(s[j][3] - mb);
            la += e0 + e1;
            lb += e2 + e3;
            pf[j >> 1][(j & 1) * 2] = pkf16(e0, e1);
            pf[j >> 1][(j & 1) * 2 + 1] = pkf16(e2, e3);
        }

        // ---- gemm2: O += P V, fp16 single pass ----
        const uint32_t fb = vb + 2 * HALF_BYTES;
#pragma unroll
        for (int m = 0; m < 2; m++) {
#pragma unroll
            for (int kc = 0; kc < 2; kc++) {
                const uint32_t ba = fb + g2off + (2 * m) * 16 * RBB + kc * 32;
                const uint32_t bb = ba + 16 * RBB;
                uint32_t bfa[4], bfb[4];
                ldsm4(ba, bfa);
                ldsm4(bb, bfb);
                mma_f16(o[4 * m], pf[kc], bfa[0], bfa[1]);
                mma_f16(o[4 * m + 1], pf[kc], bfa[2], bfa[3]);
                mma_f16(o[4 * m + 2], pf[kc], bfb[0], bfb[1]);
                mma_f16(o[4 * m + 3], pf[kc], bfb[2], bfb[3]);
            }
        }
        __syncthreads();     // all reads of buf[t&1] done
        if (t + 2 < NT) stageKV((t & 1) * BUF_BYTES, (t + 2) * BN);
        CP_COMMIT();
    }

    // ---- epilogue: max-aware merge across wc halves, normalize, store ----
    __syncthreads();
    float* Osm = (float*)SM;                       // [64][RB] f32 (buf0)
    float* Lsm = (float*)(SM + BUF_BYTES);         // [64][2]
    float* Msm = (float*)(SM + BUF_BYTES + 512);   // [64][2]
    la += __shfl_xor_sync(~0u, la, 1);
    la += __shfl_xor_sync(~0u, la, 2);
    lb += __shfl_xor_sync(~0u, lb, 1);
    lb += __shfl_xor_sync(~0u, lb, 2);
    if (tq == 0) {
        Lsm[row_a * 2 + wc] = la;
        Lsm[row_b * 2 + wc] = lb;
        Msm[row_a * 2 + wc] = ma;
        Msm[row_b * 2 + wc] = mb;
    }
    if (wc == 0) {
#pragma unroll
        for (int j = 0; j < 8; j++) {
            int cb2 = j * 8 + 2 * tq;
            Osm[row_a * RB + cb2] = o[j][0];
            Osm[row_a * RB + cb2 + 1] = o[j][1];
            Osm[row_b * RB + cb2] = o[j][2];
            Osm[row_b * RB + cb2 + 1] = o[j][3];
        }
    }
    __syncthreads();
    if (wc == 1) {
        float m0a = Msm[row_a * 2], m0b = Msm[row_b * 2];
        float msa = fmaxf(m0a, ma), msb = fmaxf(m0b, mb);
        float f0a = __expf(m0a - msa), f1a = __expf(ma - msa);
        float f0b = __expf(m0b - msb), f1b = __expf(mb - msb);
        float ia = 1.f / (Lsm[row_a * 2] * f0a + la * f1a);
        float ib = 1.f / (Lsm[row_b * 2] * f0b + lb * f1b);
        float* On = out + (size_t)n * CD * HW + q0;
#pragma unroll
        for (int j = 0; j < 8; j++) {
            int cb2 = j * 8 + 2 * tq;
            On[(size_t)cb2 * HW + row_a] =
                (o[j][0] * f1a + Osm[row_a * RB + cb2] * f0a) * ia;
            On[(size_t)(cb2 + 1) * HW + row_a] =
                (o[j][1] * f1a + Osm[row_a * RB + cb2 + 1] * f0a) * ia;
            On[(size_t)cb2 * HW + row_b] =
                (o[j][2] * f1b + Osm[row_b * RB + cb2] * f0b) * ib;
            On[(size_t)(cb2 + 1) * HW + row_b] =
                (o[j][3] * f1b + Osm[row_b * RB + cb2 + 1] * f0b) * ib;
        }
    }
}

extern "C" void kernel_launch(void* const* d_in, const int* in_sizes, int n_in,
                              void* d_out, int out_size) {
    const float* X = (const float*)d_in[0];
    float* out = (float*)d_out;
    cudaFuncSetAttribute(attn_mma, cudaFuncAttributeMaxDynamicSharedMemorySize, SMEM_TOTAL);
    convert_kernel<<<(NB * CD * HW / 4) / 256, 256>>>(X);
    attn_mma<<<dim3(HW / BM, NB), 256, SMEM_TOTAL>>>(out);
}

// round 8
// speedup vs baseline: 5.1990x; 1.1041x over previous
#include <cuda_runtime.h>
#include <cuda_fp16.h>
#include <cstdint>

#define HW 4096
#define CD 64
#define BM 64
#define BN 64
#define NT (HW / BN)
#define NB 8
#define RB 72                    // padded row length (16b elems) -> conflict-free ldmatrix
#define RBB (RB * 2)             // row bytes = 144
#define HALF_BYTES (64 * RBB)    // one sub-tile (hi or lo) = 9216B
#define KVBUF (2 * HALF_BYTES)   // hi+lo = 18432B
#define QOFF (3 * KVBUF)         // Q region after 3 KV buffers
#define SMEM_TOTAL (4 * KVBUF)   // 73728B

__device__ __align__(16) __half g_FH[NB * CD * HW];
__device__ __align__(16) __half g_FL[NB * CD * HW];

__device__ __forceinline__ uint32_t smem_u32(const void* p) {
    uint32_t a;
    asm("{ .reg .u64 t; cvta.to.shared.u64 t, %1; cvt.u32.u64 %0, t; }" : "=r"(a) : "l"(p));
    return a;
}
__device__ __forceinline__ void ldsm4(uint32_t addr, uint32_t* r) {
    asm volatile("ldmatrix.sync.aligned.m8n8.x4.shared.b16 {%0,%1,%2,%3}, [%4];"
                 : "=r"(r[0]), "=r"(r[1]), "=r"(r[2]), "=r"(r[3]) : "r"(addr));
}
__device__ __forceinline__ void ldsm4t(uint32_t addr, uint32_t* r) {
    asm volatile("ldmatrix.sync.aligned.m8n8.x4.trans.shared.b16 {%0,%1,%2,%3}, [%4];"
                 : "=r"(r[0]), "=r"(r[1]), "=r"(r[2]), "=r"(r[3]) : "r"(addr));
}
__device__ __forceinline__ void mma_f16(float* d, const uint32_t* a, uint32_t b0, uint32_t b1) {
    asm volatile(
        "mma.sync.aligned.m16n8k16.row.col.f32.f16.f16.f32 "
        "{%0,%1,%2,%3}, {%4,%5,%6,%7}, {%8,%9}, {%0,%1,%2,%3};"
        : "+f"(d[0]), "+f"(d[1]), "+f"(d[2]), "+f"(d[3])
        : "r"(a[0]), "r"(a[1]), "r"(a[2]), "r"(a[3]), "r"(b0), "r"(b1));
}
#define CP16(dst, src) asm volatile("cp.async.cg.shared.global [%0], [%1], 16;" :: "r"(dst), "l"(src))
#define CP_COMMIT()    asm volatile("cp.async.commit_group;" ::: "memory")
#define CP_WAIT2()     asm volatile("cp.async.wait_group 2;" ::: "memory")
#define CP_WAIT3()     asm volatile("cp.async.wait_group 3;" ::: "memory")

// pack two f32 -> f16x2 with a in the LOW half
__device__ __forceinline__ uint32_t pkf16(float a, float b) {
    uint32_t r;
    asm("cvt.rn.f16x2.f32 %0, %1, %2;" : "=r"(r) : "f"(b), "f"(a));
    return r;
}

// ---------------- pre-kernel: split X into fp16 hi/lo global arrays ----------------
__global__ __launch_bounds__(256) void convert_kernel(const float* __restrict__ X) {
    size_t i = (size_t)blockIdx.x * 256 + threadIdx.x;
    float4 v = reinterpret_cast<const float4*>(X)[i];
    __half hx = __float2half_rn(v.x), hy = __float2half_rn(v.y);
    __half hz = __float2half_rn(v.z), hw = __float2half_rn(v.w);
    __half lx = __float2half_rn(v.x - __half2float(hx));
    __half ly = __float2half_rn(v.y - __half2float(hy));
    __half lz = __float2half_rn(v.z - __half2float(hz));
    __half lw = __float2half_rn(v.w - __half2float(hw));
    uint2 h, l;
    h.x = (uint32_t)__half_as_ushort(hx) | ((uint32_t)__half_as_ushort(hy) << 16);
    h.y = (uint32_t)__half_as_ushort(hz) | ((uint32_t)__half_as_ushort(hw) << 16);
    l.x = (uint32_t)__half_as_ushort(lx) | ((uint32_t)__half_as_ushort(ly) << 16);
    l.y = (uint32_t)__half_as_ushort(lz) | ((uint32_t)__half_as_ushort(lw) << 16);
    reinterpret_cast<uint2*>(g_FH)[i] = h;
    reinterpret_cast<uint2*>(g_FL)[i] = l;
}

// ---------------- main attention kernel ----------------
__global__ __launch_bounds__(256, 2) void attn_mma(float* __restrict__ out) {
    extern __shared__ __align__(128) char SM[];
    const uint32_t smb = smem_u32(SM);

    const int n = blockIdx.y;
    const int q0 = blockIdx.x * BM;
    const int tid = threadIdx.x;
    const int lane = tid & 31;
    const int wid = tid >> 5;
    const int wr = wid >> 1;   // q-row group (0..3)
    const int wc = wid & 1;    // key-col group (0..1)
    const int g = lane >> 2, tq = lane & 3;
    const int r8 = lane & 7, sel = lane >> 3;

    const char* FHn = (const char*)(g_FH + (size_t)n * CD * HW);
    const char* FLn = (const char*)(g_FL + (size_t)n * CD * HW);

    // stage one hi/lo tile ([c][64] rows, 128B payload, RBB-padded), 4 CP16/thread
    auto stage = [&](uint32_t bufoff, int col0) {
#pragma unroll
        for (int i = 0; i < 4; i++) {
            int idx = i * 256 + tid;
            int half = idx >> 9;
            int c = (idx >> 3) & 63;
            int ch = idx & 7;
            const char* base = half ? FLn : FHn;
            const char* src = base + ((size_t)c * HW + col0 + ch * 8) * 2;
            uint32_t dst = smb + bufoff + half * HALF_BYTES + c * RBB + ch * 16;
            CP16(dst, src);
        }
    };

    stage(QOFF, q0);        CP_COMMIT();   // Q
    stage(0, 0);            CP_COMMIT();   // KV tile 0
    stage(KVBUF, BN);       CP_COMMIT();   // KV tile 1
    stage(2 * KVBUF, 2 * BN); CP_COMMIT(); // KV tile 2
    CP_WAIT3();             // Q resident
    __syncthreads();

    // ---- Q A-fragments (trans ldmatrix from [c][q] layout), hi+lo fp16 ----
    uint32_t qh[4][4], ql[4][4];
    {
        const uint32_t qb = smb + QOFF;
        const uint32_t lo = ((sel >> 1) * 8 + r8) * RBB + (wr * 16 + (sel & 1) * 8) * 2;
#pragma unroll
        for (int ch = 0; ch < 4; ch++) {
            ldsm4t(qb + ch * 16 * RBB + lo, qh[ch]);
            ldsm4t(qb + HALF_BYTES + ch * 16 * RBB + lo, ql[ch]);
        }
    }

    const int row_a = wr * 16 + g, row_b = row_a + 8;

    float o[8][4];
#pragma unroll
    for (int j = 0; j < 8; j++)
#pragma unroll
        for (int r = 0; r < 4; r++) o[j][r] = 0.f;
    float la = 0.f, lb = 0.f;
    float ma = -1e30f, mb = -1e30f;

    const uint32_t g1off = ((sel & 1) * 8 + r8) * RBB + (wc * 32 + (sel >> 1) * 8) * 2;
    const uint32_t g2off = ((sel >> 1) * 8 + r8) * RBB + (wc * 32 + (sel & 1) * 8) * 2;

    int buf = 0;
    for (int t = 0; t < NT; t++) {
        CP_WAIT2();          // tile t resident (t+1, t+2 may still be in flight)
        __syncthreads();
        const uint32_t vb = smb + buf * KVBUF;

        // ---- gemm1: S = Q Kt, fp16 3 split passes, accumulator-interleaved ----
        float s[4][4];
#pragma unroll
        for (int j = 0; j < 4; j++)
#pragma unroll
            for (int r = 0; r < 4; r++) s[j][r] = 0.f;
#pragma unroll
        for (int ch = 0; ch < 4; ch++) {
            const uint32_t base = vb + g1off + ch * 16 * RBB;
            uint32_t bh0[4], bl0[4], bh1[4], bl1[4];
            ldsm4t(base, bh0);
            ldsm4t(base + HALF_BYTES, bl0);
            ldsm4t(base + 32, bh1);
            ldsm4t(base + 32 + HALF_BYTES, bl1);
            mma_f16(s[0], qh[ch], bh0[0], bh0[1]);
            mma_f16(s[1], qh[ch], bh0[2], bh0[3]);
            mma_f16(s[2], qh[ch], bh1[0], bh1[1]);
            mma_f16(s[3], qh[ch], bh1[2], bh1[3]);
            mma_f16(s[0], qh[ch], bl0[0], bl0[1]);
            mma_f16(s[1], qh[ch], bl0[2], bl0[3]);
            mma_f16(s[2], qh[ch], bl1[0], bl1[1]);
            mma_f16(s[3], qh[ch], bl1[2], bl1[3]);
            mma_f16(s[0], ql[ch], bh0[0], bh0[1]);
            mma_f16(s[1], ql[ch], bh0[2], bh0[3]);
            mma_f16(s[2], ql[ch], bh1[0], bh1[1]);
            mma_f16(s[3], ql[ch], bh1[2], bh1[3]);
        }

        // ---- online softmax (FA2, per warp-half), skip rescale when max unchanged ----
        float am = fmaxf(fmaxf(s[0][0], s[0][1]), fmaxf(s[1][0], s[1][1]));
        am = fmaxf(am, fmaxf(fmaxf(s[2][0], s[2][1]), fmaxf(s[3][0], s[3][1])));
        float bm = fmaxf(fmaxf(s[0][2], s[0][3]), fmaxf(s[1][2], s[1][3]));
        bm = fmaxf(bm, fmaxf(fmaxf(s[2][2], s[2][3]), fmaxf(s[3][2], s[3][3])));
        am = fmaxf(am, __shfl_xor_sync(~0u, am, 1));
        am = fmaxf(am, __shfl_xor_sync(~0u, am, 2));
        bm = fmaxf(bm, __shfl_xor_sync(~0u, bm, 1));
        bm = fmaxf(bm, __shfl_xor_sync(~0u, bm, 2));
        if (__any_sync(~0u, (am > ma) | (bm > mb))) {
            float man = fmaxf(ma, am), mbn = fmaxf(mb, bm);
            float ca = __expf(ma - man), cb = __expf(mb - mbn);
            ma = man;
            mb = mbn;
            la *= ca;
            lb *= cb;
#pragma unroll
            for (int j = 0; j < 8; j++) {
                o[j][0] *= ca;
                o[j][1] *= ca;
                o[j][2] *= cb;
                o[j][3] *= cb;
            }
        }

        uint32_t pf[2][4];
#pragma unroll
        for (int j = 0; j < 4; j++) {
            float e0 = __expf(s[j][0] - ma), e1 = __expf(s[j][1] - ma);
            float e2 = __expf(s[j][2] - mb), e3 = __expf(s[j][3] - mb);
            la += e0 + e1;
            lb += e2 + e3;
            pf[j >> 1][(j & 1) * 2] = pkf16(e0, e1);
            pf[j >> 1][(j & 1) * 2 + 1] = pkf16(e2, e3);
        }

        // ---- gemm2: O += P V, fp16-hi single pass ----
#pragma unroll
        for (int m = 0; m < 2; m++) {
#pragma unroll
            for (int kc = 0; kc < 2; kc++) {
                const uint32_t ba = vb + g2off + (2 * m) * 16 * RBB + kc * 32;
                const uint32_t bb = ba + 16 * RBB;
                uint32_t bfa[4], bfb[4];
                ldsm4(ba, bfa);
                ldsm4(bb, bfb);
                mma_f16(o[4 * m], pf[kc], bfa[0], bfa[1]);
                mma_f16(o[4 * m + 1], pf[kc], bfa[2], bfa[3]);
                mma_f16(o[4 * m + 2], pf[kc], bfb[0], bfb[1]);
                mma_f16(o[4 * m + 3], pf[kc], bfb[2], bfb[3]);
            }
        }
        __syncthreads();     // all reads of this buffer done
        if (t + 3 < NT) stage(buf * KVBUF, (t + 3) * BN);
        CP_COMMIT();
        buf = (buf == 2) ? 0 : buf + 1;
    }

    // ---- epilogue: max-aware merge across wc halves, normalize, store ----
    __syncthreads();
    float* Osm = (float*)SM;                     // [64][RB] f32 (buf0)
    float* Lsm = (float*)(SM + KVBUF);           // [64][2]  (buf1)
    float* Msm = (float*)(SM + KVBUF + 512);     // [64][2]
    la += __shfl_xor_sync(~0u, la, 1);
    la += __shfl_xor_sync(~0u, la, 2);
    lb += __shfl_xor_sync(~0u, lb, 1);
    lb += __shfl_xor_sync(~0u, lb, 2);
    if (tq == 0) {
        Lsm[row_a * 2 + wc] = la;
        Lsm[row_b * 2 + wc] = lb;
        Msm[row_a * 2 + wc] = ma;
        Msm[row_b * 2 + wc] = mb;
    }
    if (wc == 0) {
#pragma unroll
        for (int j = 0; j < 8; j++) {
            int cb2 = j * 8 + 2 * tq;
            Osm[row_a * RB + cb2] = o[j][0];
            Osm[row_a * RB + cb2 + 1] = o[j][1];
            Osm[row_b * RB + cb2] = o[j][2];
            Osm[row_b * RB + cb2 + 1] = o[j][3];
        }
    }
    __syncthreads();
    if (wc == 1) {
        float m0a = Msm[row_a * 2], m0b = Msm[row_b * 2];
        float msa = fmaxf(m0a, ma), msb = fmaxf(m0b, mb);
        float f0a = __expf(m0a - msa), f1a = __expf(ma - msa);
        float f0b = __expf(m0b - msb), f1b = __expf(mb - msb);
        float ia = 1.f / (Lsm[row_a * 2] * f0a + la * f1a);
        float ib = 1.f / (Lsm[row_b * 2] * f0b + lb * f1b);
        float* On = out + (size_t)n * CD * HW + q0;
#pragma unroll
        for (int j = 0; j < 8; j++) {
            int cb2 = j * 8 + 2 * tq;
            On[(size_t)cb2 * HW + row_a] =
                (o[j][0] * f1a + Osm[row_a * RB + cb2] * f0a) * ia;
            On[(size_t)(cb2 + 1) * HW + row_a] =
                (o[j][1] * f1a + Osm[row_a * RB + cb2 + 1] * f0a) * ia;
            On[(size_t)cb2 * HW + row_b] =
                (o[j][2] * f1b + Osm[row_b * RB + cb2] * f0b) * ib;
            On[(size_t)(cb2 + 1) * HW + row_b] =
                (o[j][3] * f1b + Osm[row_b * RB + cb2 + 1] * f0b) * ib;
        }
    }
}

extern "C" void kernel_launch(void* const* d_in, const int* in_sizes, int n_in,
                              void* d_out, int out_size) {
    const float* X = (const float*)d_in[0];
    float* out = (float*)d_out;
    cudaFuncSetAttribute(attn_mma, cudaFuncAttributeMaxDynamicSharedMemorySize, SMEM_TOTAL);
    convert_kernel<<<(NB * CD * HW / 4) / 256, 256>>>(X);
    attn_mma<<<dim3(HW / BM, NB), 256, SMEM_TOTAL>>>(out);
}

// round 9
// speedup vs baseline: 5.3493x; 1.0289x over previous
#include <cuda_runtime.h>
#include <cuda_fp16.h>
#include <cstdint>

#define HW 4096
#define CD 64
#define BM 64
#define BN 64
#define NT (HW / BN)
#define NB 8
#define RB 72                    // padded row length (16b elems) -> conflict-free ldmatrix
#define RBB (RB * 2)             // row bytes = 144
#define HALF_BYTES (64 * RBB)    // one sub-tile (hi or lo) = 9216B
#define KVBUF (2 * HALF_BYTES)   // hi+lo = 18432B
#define QOFF (2 * KVBUF)         // Q region after 2 KV buffers
#define SMEM_TOTAL (3 * KVBUF)   // 55296B -> 4 CTAs/SM

__device__ __align__(16) __half g_FH[NB * CD * HW];
__device__ __align__(16) __half g_FL[NB * CD * HW];

__device__ __forceinline__ uint32_t smem_u32(const void* p) {
    uint32_t a;
    asm("{ .reg .u64 t; cvta.to.shared.u64 t, %1; cvt.u32.u64 %0, t; }" : "=r"(a) : "l"(p));
    return a;
}
__device__ __forceinline__ void ldsm4(uint32_t addr, uint32_t* r) {
    asm volatile("ldmatrix.sync.aligned.m8n8.x4.shared.b16 {%0,%1,%2,%3}, [%4];"
                 : "=r"(r[0]), "=r"(r[1]), "=r"(r[2]), "=r"(r[3]) : "r"(addr));
}
__device__ __forceinline__ void ldsm4t(uint32_t addr, uint32_t* r) {
    asm volatile("ldmatrix.sync.aligned.m8n8.x4.trans.shared.b16 {%0,%1,%2,%3}, [%4];"
                 : "=r"(r[0]), "=r"(r[1]), "=r"(r[2]), "=r"(r[3]) : "r"(addr));
}
__device__ __forceinline__ void mma_f16(float* d, const uint32_t* a, uint32_t b0, uint32_t b1) {
    asm volatile(
        "mma.sync.aligned.m16n8k16.row.col.f32.f16.f16.f32 "
        "{%0,%1,%2,%3}, {%4,%5,%6,%7}, {%8,%9}, {%0,%1,%2,%3};"
        : "+f"(d[0]), "+f"(d[1]), "+f"(d[2]), "+f"(d[3])
        : "r"(a[0]), "r"(a[1]), "r"(a[2]), "r"(a[3]), "r"(b0), "r"(b1));
}
#define CP16(dst, src) asm volatile("cp.async.cg.shared.global [%0], [%1], 16;" :: "r"(dst), "l"(src))
#define CP_COMMIT()    asm volatile("cp.async.commit_group;" ::: "memory")
#define CP_WAIT1()     asm volatile("cp.async.wait_group 1;" ::: "memory")
#define CP_WAIT2()     asm volatile("cp.async.wait_group 2;" ::: "memory")

// pack two f32 -> f16x2 with a in the LOW half
__device__ __forceinline__ uint32_t pkf16(float a, float b) {
    uint32_t r;
    asm("cvt.rn.f16x2.f32 %0, %1, %2;" : "=r"(r) : "f"(b), "f"(a));
    return r;
}

// ---------------- pre-kernel: split X into fp16 hi/lo global arrays ----------------
__global__ __launch_bounds__(256) void convert_kernel(const float* __restrict__ X) {
    size_t i = (size_t)blockIdx.x * 256 + threadIdx.x;
    float4 v = reinterpret_cast<const float4*>(X)[i];
    __half hx = __float2half_rn(v.x), hy = __float2half_rn(v.y);
    __half hz = __float2half_rn(v.z), hw = __float2half_rn(v.w);
    __half lx = __float2half_rn(v.x - __half2float(hx));
    __half ly = __float2half_rn(v.y - __half2float(hy));
    __half lz = __float2half_rn(v.z - __half2float(hz));
    __half lw = __float2half_rn(v.w - __half2float(hw));
    uint2 h, l;
    h.x = (uint32_t)__half_as_ushort(hx) | ((uint32_t)__half_as_ushort(hy) << 16);
    h.y = (uint32_t)__half_as_ushort(hz) | ((uint32_t)__half_as_ushort(hw) << 16);
    l.x = (uint32_t)__half_as_ushort(lx) | ((uint32_t)__half_as_ushort(ly) << 16);
    l.y = (uint32_t)__half_as_ushort(lz) | ((uint32_t)__half_as_ushort(lw) << 16);
    reinterpret_cast<uint2*>(g_FH)[i] = h;
    reinterpret_cast<uint2*>(g_FL)[i] = l;
}

// ---------------- main attention kernel: 128 threads, 4 warps, each 16q x 64k ----------------
__global__ __launch_bounds__(128, 4) void attn_mma(float* __restrict__ out) {
    extern __shared__ __align__(128) char SM[];
    const uint32_t smb = smem_u32(SM);

    const int n = blockIdx.y;
    const int q0 = blockIdx.x * BM;
    const int tid = threadIdx.x;
    const int lane = tid & 31;
    const int wid = tid >> 5;          // q-row group: rows wid*16 .. wid*16+15
    const int g = lane >> 2, tq = lane & 3;
    const int r8 = lane & 7, sel = lane >> 3;

    const char* FHn = (const char*)(g_FH + (size_t)n * CD * HW);
    const char* FLn = (const char*)(g_FL + (size_t)n * CD * HW);

    // stage one hi/lo tile ([c][64] rows, 128B payload, RBB-padded), 8 CP16/thread
    auto stage = [&](uint32_t bufoff, int col0) {
#pragma unroll
        for (int i = 0; i < 8; i++) {
            int idx = i * 128 + tid;
            int half = idx >> 9;
            int c = (idx >> 3) & 63;
            int ch = idx & 7;
            const char* base = half ? FLn : FHn;
            const char* src = base + ((size_t)c * HW + col0 + ch * 8) * 2;
            uint32_t dst = smb + bufoff + half * HALF_BYTES + c * RBB + ch * 16;
            CP16(dst, src);
        }
    };

    stage(QOFF, q0);     CP_COMMIT();   // Q
    stage(0, 0);         CP_COMMIT();   // KV tile 0
    stage(KVBUF, BN);    CP_COMMIT();   // KV tile 1
    CP_WAIT2();          // Q resident
    __syncthreads();

    // ---- Q A-fragments (trans ldmatrix from [c][q] layout), hi+lo fp16 ----
    uint32_t qh[4][4], ql[4][4];
    {
        const uint32_t qb = smb + QOFF;
        const uint32_t lo = ((sel >> 1) * 8 + r8) * RBB + (wid * 16 + (sel & 1) * 8) * 2;
#pragma unroll
        for (int ch = 0; ch < 4; ch++) {
            ldsm4t(qb + ch * 16 * RBB + lo, qh[ch]);
            ldsm4t(qb + HALF_BYTES + ch * 16 * RBB + lo, ql[ch]);
        }
    }

    const int row_a = wid * 16 + g, row_b = row_a + 8;

    float o[8][4];
#pragma unroll
    for (int j = 0; j < 8; j++)
#pragma unroll
        for (int r = 0; r < 4; r++) o[j][r] = 0.f;
    float la = 0.f, lb = 0.f;
    float ma = -1e30f, mb = -1e30f;

    const uint32_t g1off = ((sel & 1) * 8 + r8) * RBB + ((sel >> 1) * 8) * 2;
    const uint32_t g2off = ((sel >> 1) * 8 + r8) * RBB + ((sel & 1) * 8) * 2;

    for (int t = 0; t < NT; t++) {
        CP_WAIT1();          // tile t resident (t+1 may still be in flight)
        __syncthreads();
        const uint32_t vb = smb + (t & 1) * KVBUF;

        // ---- gemm1: S(16x64) = Q Kt, fp16 3 split passes ----
        float s[8][4];
#pragma unroll
        for (int j = 0; j < 8; j++)
#pragma unroll
            for (int r = 0; r < 4; r++) s[j][r] = 0.f;
#pragma unroll
        for (int ch = 0; ch < 4; ch++) {
            const uint32_t base = vb + g1off + ch * 16 * RBB;
#pragma unroll
            for (int kp = 0; kp < 2; kp++) {   // key-group pairs: kg = 2kp, 2kp+1
                const uint32_t ka = base + (2 * kp) * 32;
                const uint32_t kb = ka + 32;
                uint32_t bh0[4], bl0[4], bh1[4], bl1[4];
                ldsm4t(ka, bh0);
                ldsm4t(ka + HALF_BYTES, bl0);
                ldsm4t(kb, bh1);
                ldsm4t(kb + HALF_BYTES, bl1);
                float* s0 = s[4 * kp], * s1 = s[4 * kp + 1];
                float* s2 = s[4 * kp + 2], * s3 = s[4 * kp + 3];
                mma_f16(s0, qh[ch], bh0[0], bh0[1]);
                mma_f16(s1, qh[ch], bh0[2], bh0[3]);
                mma_f16(s2, qh[ch], bh1[0], bh1[1]);
                mma_f16(s3, qh[ch], bh1[2], bh1[3]);
                mma_f16(s0, qh[ch], bl0[0], bl0[1]);
                mma_f16(s1, qh[ch], bl0[2], bl0[3]);
                mma_f16(s2, qh[ch], bl1[0], bl1[1]);
                mma_f16(s3, qh[ch], bl1[2], bl1[3]);
                mma_f16(s0, ql[ch], bh0[0], bh0[1]);
                mma_f16(s1, ql[ch], bh0[2], bh0[3]);
                mma_f16(s2, ql[ch], bh1[0], bh1[1]);
                mma_f16(s3, ql[ch], bh1[2], bh1[3]);
            }
        }

        // ---- online softmax (FA2), rows fully warp-local ----
        float am = -1e30f, bm = -1e30f;
#pragma unroll
        for (int f = 0; f < 8; f++) {
            am = fmaxf(am, fmaxf(s[f][0], s[f][1]));
            bm = fmaxf(bm, fmaxf(s[f][2], s[f][3]));
        }
        am = fmaxf(am, __shfl_xor_sync(~0u, am, 1));
        am = fmaxf(am, __shfl_xor_sync(~0u, am, 2));
        bm = fmaxf(bm, __shfl_xor_sync(~0u, bm, 1));
        bm = fmaxf(bm, __shfl_xor_sync(~0u, bm, 2));
        if (__any_sync(~0u, (am > ma) | (bm > mb))) {
            float man = fmaxf(ma, am), mbn = fmaxf(mb, bm);
            float ca = __expf(ma - man), cb = __expf(mb - mbn);
            ma = man;
            mb = mbn;
            la *= ca;
            lb *= cb;
#pragma unroll
            for (int j = 0; j < 8; j++) {
                o[j][0] *= ca;
                o[j][1] *= ca;
                o[j][2] *= cb;
                o[j][3] *= cb;
            }
        }

        uint32_t pf[4][4];
#pragma unroll
        for (int kc = 0; kc < 4; kc++) {
            float e0 = __expf(s[2 * kc][0] - ma), e1 = __expf(s[2 * kc][1] - ma);
            float e2 = __expf(s[2 * kc][2] - mb), e3 = __expf(s[2 * kc][3] - mb);
            float e4 = __expf(s[2 * kc + 1][0] - ma), e5 = __expf(s[2 * kc + 1][1] - ma);
            float e6 = __expf(s[2 * kc + 1][2] - mb), e7 = __expf(s[2 * kc + 1][3] - mb);
            la += e0 + e1 + e4 + e5;
            lb += e2 + e3 + e6 + e7;
            pf[kc][0] = pkf16(e0, e1);
            pf[kc][1] = pkf16(e2, e3);
            pf[kc][2] = pkf16(e4, e5);
            pf[kc][3] = pkf16(e6, e7);
        }

        // ---- gemm2: O(16x64) += P V, fp16 single pass ----
#pragma unroll
        for (int kc = 0; kc < 4; kc++) {
#pragma unroll
            for (int mp = 0; mp < 2; mp++) {
                const uint32_t ba = vb + g2off + (2 * mp) * 16 * RBB + kc * 32;
                const uint32_t bb = ba + 16 * RBB;
                uint32_t bfa[4], bfb[4];
                ldsm4(ba, bfa);
                ldsm4(bb, bfb);
                mma_f16(o[4 * mp], pf[kc], bfa[0], bfa[1]);
                mma_f16(o[4 * mp + 1], pf[kc], bfa[2], bfa[3]);
                mma_f16(o[4 * mp + 2], pf[kc], bfb[0], bfb[1]);
                mma_f16(o[4 * mp + 3], pf[kc], bfb[2], bfb[3]);
            }
        }
        __syncthreads();     // all warps done reading buf t%2
        if (t + 2 < NT) stage((t & 1) * KVBUF, (t + 2) * BN);
        CP_COMMIT();
    }

    // ---- epilogue: rows warp-local -> direct normalize + store ----
    la += __shfl_xor_sync(~0u, la, 1);
    la += __shfl_xor_sync(~0u, la, 2);
    lb += __shfl_xor_sync(~0u, lb, 1);
    lb += __shfl_xor_sync(~0u, lb, 2);
    const float ia = 1.f / la, ib = 1.f / lb;
    float* On = out + (size_t)n * CD * HW + q0;
#pragma unroll
    for (int j = 0; j < 8; j++) {
        int cb2 = j * 8 + 2 * tq;
        On[(size_t)cb2 * HW + row_a] = o[j][0] * ia;
        On[(size_t)(cb2 + 1) * HW + row_a] = o[j][1] * ia;
        On[(size_t)cb2 * HW + row_b] = o[j][2] * ib;
        On[(size_t)(cb2 + 1) * HW + row_b] = o[j][3] * ib;
    }
}

extern "C" void kernel_launch(void* const* d_in, const int* in_sizes, int n_in,
                              void* d_out, int out_size) {
    const float* X = (const float*)d_in[0];
    float* out = (float*)d_out;
    cudaFuncSetAttribute(attn_mma, cudaFuncAttributeMaxDynamicSharedMemorySize, SMEM_TOTAL);
    convert_kernel<<<(NB * CD * HW / 4) / 256, 256>>>(X);
    attn_mma<<<dim3(HW / BM, NB), 128, SMEM_TOTAL>>>(out);
}